// round 16
// baseline (speedup 1.0000x reference)
#include <cuda_runtime.h>
#include <cuda_bf16.h>
#include <cstdint>

// x:   [B=64, C=12, 224, 224] fp32
// w:   [C=12, E=768] fp32
// out: [B=64, P=196, E=768] fp32
//
// R15 skeleton (best: CTA = one patch pair, 192 thr / 6 warps, warp pools 2
// channels via 8 staged LDG.128) with a packed-f32x2 epilogue:
//  - w columns loaded as ulonglong2 (LDG.128, halves feed fma.rn.f32x2)
//  - pooled stored duplicated as float2(s,s) -> LDS.64 gives the broadcast
//    multiplier pair with zero packing instructions
//  - 48 FFMA2 replaces 96 scalar FFMA per thread (tail -36%)

#define IMG    224
#define NP     14
#define C_IN   12
#define EMBED  768
#define NTH    192
#define CH_STRIDE ((size_t)IMG * IMG)   // floats between channels

using u64t = unsigned long long;

__device__ __forceinline__ u64t ffma2(u64t a, u64t b, u64t c) {
    u64t d;
    asm("fma.rn.f32x2 %0, %1, %2, %3;" : "=l"(d) : "l"(a), "l"(b), "l"(c));
    return d;
}

__global__ __launch_bounds__(NTH, 6) void patch_pair_f32x2_kernel(
    const float* __restrict__ x,
    const float* __restrict__ w,
    float* __restrict__ out)
{
    const int pp  = blockIdx.x;        // patch-col pair 0..6
    const int pi  = blockIdx.y;        // patch row 0..13
    const int b   = blockIdx.z;        // 0..63
    const int t   = threadIdx.x;
    const int warp = t >> 5;           // 0..5 -> channels 2w, 2w+1
    const int lane = t & 31;
    const int q8  = lane & 7;          // float4 col within the 32-float row
    const int rh  = lane >> 3;         // row phase 0..3

    __shared__ __align__(8) float2 pooled2[C_IN][2];  // [channel][patch], (s,s)

    // ---- Phase 1: warp pools 16x32 of channels 2w and 2w+1 ----
    const float* base0 = x
        + (((size_t)(b * C_IN + 2 * warp)) * IMG + (size_t)pi * 16 + rh) * IMG
        + (size_t)pp * 32 + q8 * 4;
    const float* base1 = base0 + CH_STRIDE;

    // 8 independent LDG.128 (rows rh+4k, k=0..3, for both channels)
    float4 a0 = *reinterpret_cast<const float4*>(base0 + (size_t)(4 * 0) * IMG);
    float4 a1 = *reinterpret_cast<const float4*>(base0 + (size_t)(4 * 1) * IMG);
    float4 a2 = *reinterpret_cast<const float4*>(base0 + (size_t)(4 * 2) * IMG);
    float4 a3 = *reinterpret_cast<const float4*>(base0 + (size_t)(4 * 3) * IMG);
    float4 b0 = *reinterpret_cast<const float4*>(base1 + (size_t)(4 * 0) * IMG);
    float4 b1 = *reinterpret_cast<const float4*>(base1 + (size_t)(4 * 1) * IMG);
    float4 b2 = *reinterpret_cast<const float4*>(base1 + (size_t)(4 * 2) * IMG);
    float4 b3 = *reinterpret_cast<const float4*>(base1 + (size_t)(4 * 3) * IMG);

    float s0 = (((a0.x + a0.y) + (a0.z + a0.w)) + ((a1.x + a1.y) + (a1.z + a1.w)))
             + (((a2.x + a2.y) + (a2.z + a2.w)) + ((a3.x + a3.y) + (a3.z + a3.w)));
    float s1 = (((b0.x + b0.y) + (b0.z + b0.w)) + ((b1.x + b1.y) + (b1.z + b1.w)))
             + (((b2.x + b2.y) + (b2.z + b2.w)) + ((b3.x + b3.y) + (b3.z + b3.w)));

    // Fold lane bits 0,1 (float4 cols within a patch) and 3,4 (row phases);
    // bit 2 (q8>>2) = patch column survives.
    s0 += __shfl_xor_sync(0xffffffffu, s0, 1);
    s1 += __shfl_xor_sync(0xffffffffu, s1, 1);
    s0 += __shfl_xor_sync(0xffffffffu, s0, 2);
    s1 += __shfl_xor_sync(0xffffffffu, s1, 2);
    s0 += __shfl_xor_sync(0xffffffffu, s0, 8);
    s1 += __shfl_xor_sync(0xffffffffu, s1, 8);
    s0 += __shfl_xor_sync(0xffffffffu, s0, 16);
    s1 += __shfl_xor_sync(0xffffffffu, s1, 16);

    if ((lane & 27) == 0) {            // lanes 0 and 4
        const int pc = (lane >> 2) & 1;
        pooled2[2 * warp + 0][pc] = make_float2(s0, s0);
        pooled2[2 * warp + 1][pc] = make_float2(s1, s1);
    }
    __syncthreads();

    // ---- Phase 2: packed f32x2 epilogue, two patch outputs per thread ----
    u64t acc0lo = 0, acc0hi = 0;       // patch col 0: (e,e+1) and (e+2,e+3)
    u64t acc1lo = 0, acc1hi = 0;       // patch col 1
    #pragma unroll
    for (int c = 0; c < C_IN; ++c) {
        const ulonglong2 wv =
            *reinterpret_cast<const ulonglong2*>(&w[c * EMBED + t * 4]);
        const u64t p0 = *reinterpret_cast<const u64t*>(&pooled2[c][0]);
        const u64t p1 = *reinterpret_cast<const u64t*>(&pooled2[c][1]);
        acc0lo = ffma2(p0, wv.x, acc0lo);
        acc0hi = ffma2(p0, wv.y, acc0hi);
        acc1lo = ffma2(p1, wv.x, acc1lo);
        acc1hi = ffma2(p1, wv.y, acc1hi);
    }

    float* o = out + ((size_t)b * (NP * NP) + (size_t)pi * NP + pp * 2) * EMBED + t * 4;
    ulonglong2 r0; r0.x = acc0lo; r0.y = acc0hi;
    ulonglong2 r1; r1.x = acc1lo; r1.y = acc1hi;
    *reinterpret_cast<ulonglong2*>(o)         = r0;   // patch (pi, 2pp)
    *reinterpret_cast<ulonglong2*>(o + EMBED) = r1;   // patch (pi, 2pp+1)
}

extern "C" void kernel_launch(void* const* d_in, const int* in_sizes, int n_in,
                              void* d_out, int out_size)
{
    const float* x = (const float*)d_in[0];
    const float* w = (const float*)d_in[1];
    float* out = (float*)d_out;

    dim3 grid(7, NP, 64);   // 6272 CTAs
    patch_pair_f32x2_kernel<<<grid, NTH>>>(x, w, out);
}